// round 14
// baseline (speedup 1.0000x reference)
#include <cuda_runtime.h>
#include <cuda_bf16.h>
#include <math.h>
#include <stdint.h>

#define Bn   32
#define Nn   1024
#define FIN  512
#define H1n  256
#define H2n  128

typedef __nv_bfloat16 bf16;
typedef __nv_bfloat162 bf162;

// ---- scratch (device globals; no allocation allowed) ----
__device__ bf16 g_xh[Bn * Nn * FIN];
__device__ bf16 g_xl[Bn * Nn * FIN];
__device__ bf16 g_w1h[FIN * H1n];
__device__ bf16 g_w1l[FIN * H1n];
__device__ bf16 g_w2h[H1n * H2n];
__device__ bf16 g_w2l[H1n * H2n];
__device__ bf16 g_h1h[Bn * Nn * H1n];
__device__ bf16 g_h1l[Bn * Nn * H1n];
__device__ bf16 g_g1h[Bn * Nn * H1n];
__device__ bf16 g_g1l[Bn * Nn * H1n];
__device__ bf16 g_h2h[Bn * Nn * H2n];
__device__ bf16 g_h2l[Bn * Nn * H2n];
__device__ float g_el[Bn * Nn];
__device__ float g_er[Bn * Nn];
__device__ float g_sb[Bn * 2];
__device__ float g_v[Bn * Nn];

// ============================================================
// PTX helpers (all sm_80-era, valid at compute_103)
// ============================================================
__device__ __forceinline__ uint32_t smem_u32(const void* p) {
    uint32_t a;
    asm("{ .reg .u64 t; cvta.to.shared.u64 t, %1; cvt.u32.u64 %0, t; }"
        : "=r"(a) : "l"(p));
    return a;
}
__device__ __forceinline__ void ldsm4(uint32_t* r, uint32_t addr) {
    asm volatile("ldmatrix.sync.aligned.m8n8.x4.shared.b16 {%0,%1,%2,%3}, [%4];"
        : "=r"(r[0]), "=r"(r[1]), "=r"(r[2]), "=r"(r[3]) : "r"(addr));
}
__device__ __forceinline__ void ldsm4t(uint32_t* r, uint32_t addr) {
    asm volatile("ldmatrix.sync.aligned.m8n8.x4.trans.shared.b16 {%0,%1,%2,%3}, [%4];"
        : "=r"(r[0]), "=r"(r[1]), "=r"(r[2]), "=r"(r[3]) : "r"(addr));
}
__device__ __forceinline__ void mma16816(float* d, const uint32_t* a, const uint32_t* b) {
    asm volatile(
        "mma.sync.aligned.m16n8k16.row.col.f32.bf16.bf16.f32 "
        "{%0,%1,%2,%3}, {%4,%5,%6,%7}, {%8,%9}, {%0,%1,%2,%3};"
        : "+f"(d[0]), "+f"(d[1]), "+f"(d[2]), "+f"(d[3])
        : "r"(a[0]), "r"(a[1]), "r"(a[2]), "r"(a[3]), "r"(b[0]), "r"(b[1]));
}
__device__ __forceinline__ void cp16(uint32_t saddr, const void* g) {
    asm volatile("cp.async.cg.shared.global [%0], [%1], 16;"
        :: "r"(saddr), "l"(g));
}
__device__ __forceinline__ void cp_commit() {
    asm volatile("cp.async.commit_group;");
}
template<int N> __device__ __forceinline__ void cp_wait() {
    asm volatile("cp.async.wait_group %0;" :: "n"(N));
}
__device__ __forceinline__ bf162 split_hi2(float a, float b, bf162& lo) {
    bf162 hi;
    hi.x = __float2bfloat16_rn(a);
    hi.y = __float2bfloat16_rn(b);
    lo.x = __float2bfloat16_rn(a - __bfloat162float(hi.x));
    lo.y = __float2bfloat16_rn(b - __bfloat162float(hi.y));
    return hi;
}

// SMEM stage geometry (bytes)
#define A_ARR   10240            // 128 x 40 bf16
#define B_ARR   8704             // 32 x 136 bf16
#define STG_SZ  (2*A_ARR + 2*B_ARR)   // 37888
#define DSM_SZ  (2*STG_SZ)            // 75776

// ============================================================
// fp32 -> bf16 hi/lo split
// ============================================================
__global__ __launch_bounds__(256) void split_kernel(
    const float* __restrict__ src, bf16* __restrict__ hi,
    bf16* __restrict__ lo, int n4)
{
    int i = blockIdx.x * blockDim.x + threadIdx.x;
    if (i >= n4) return;
    float4 v = ((const float4*)src)[i];
    bf162 h0l, h1l2;
    bf162 h0 = split_hi2(v.x, v.y, h0l);
    bf162 h1 = split_hi2(v.z, v.w, h1l2);
    ((bf162*)hi)[i * 2]     = h0;
    ((bf162*)hi)[i * 2 + 1] = h1;
    ((bf162*)lo)[i * 2]     = h0l;
    ((bf162*)lo)[i * 2 + 1] = h1l2;
}

// ============================================================
// Dense GEMM, cp.async double-buffered, split-bf16 in/out.
// CTA 128m x 128n, 8 warps, warp 32m x 64n, K chunks of 32.
// ============================================================
template<int K>
__global__ __launch_bounds__(256) void mma_gemm_kernel(
    const bf16* __restrict__ Ah, const bf16* __restrict__ Al,
    const bf16* __restrict__ Bh, const bf16* __restrict__ Bl,
    bf16* __restrict__ Ch, bf16* __restrict__ Cl, int N)
{
    extern __shared__ char dsm[];
    const uint32_t base = smem_u32(dsm);

    const int t = threadIdx.x;
    const int bm = blockIdx.y * 128, bn = blockIdx.x * 128;
    const int w = t >> 5, l = t & 31;
    const int wi0 = (w & 3) * 32;
    const int wf0 = (w >> 2) * 64;

    const int ar = t >> 1, ac = (t & 1) * 16;
    const int br = t >> 3, bc = (t & 7) * 16;
    const uint32_t aoff = (uint32_t)(ar * 40 + ac) * 2;
    const uint32_t boff = (uint32_t)(br * 136 + bc) * 2;

    float acc[2][8][4];
#pragma unroll
    for (int m = 0; m < 2; m++)
#pragma unroll
        for (int n = 0; n < 8; n++)
#pragma unroll
            for (int q = 0; q < 4; q++) acc[m][n][q] = 0.f;

    auto load_chunk = [&](int k0, int s) {
        uint32_t sb = base + (uint32_t)s * STG_SZ;
        const bf16* pa = Ah + (size_t)(bm + ar) * K + k0 + ac;
        const bf16* pl = Al + (size_t)(bm + ar) * K + k0 + ac;
        cp16(sb + aoff, pa);            cp16(sb + aoff + 16, pa + 8);
        cp16(sb + A_ARR + aoff, pl);    cp16(sb + A_ARR + aoff + 16, pl + 8);
        const bf16* pbh = Bh + (size_t)(k0 + br) * N + bn + bc;
        const bf16* pbl = Bl + (size_t)(k0 + br) * N + bn + bc;
        uint32_t bb = sb + 2 * A_ARR;
        cp16(bb + boff, pbh);           cp16(bb + boff + 16, pbh + 8);
        cp16(bb + B_ARR + boff, pbl);   cp16(bb + B_ARR + boff + 16, pbl + 8);
    };

    const uint32_t lrow = (uint32_t)(l & 15), lhalf = (uint32_t)(l >> 4);
    constexpr int NCH = K / 32;

    load_chunk(0, 0);
    cp_commit();

    for (int ch = 0; ch < NCH; ch++) {
        const int s = ch & 1;
        if (ch + 1 < NCH) {
            load_chunk((ch + 1) * 32, s ^ 1);
            cp_commit();
            cp_wait<1>();
        } else {
            cp_wait<0>();
        }
        __syncthreads();
        const uint32_t aH = base + (uint32_t)s * STG_SZ;
        const uint32_t aL = aH + A_ARR;
        const uint32_t bH = aH + 2 * A_ARR;
        const uint32_t bL = bH + B_ARR;
#pragma unroll
        for (int ks = 0; ks < 2; ks++) {
            uint32_t ah[2][4], al2[2][4];
            uint32_t abase = (uint32_t)((wi0 + lrow) * 80 + ks * 32 + lhalf * 16);
            ldsm4(ah[0],  aH + abase);
            ldsm4(ah[1],  aH + abase + 16 * 80);
            ldsm4(al2[0], aL + abase);
            ldsm4(al2[1], aL + abase + 16 * 80);
#pragma unroll
            for (int nb2 = 0; nb2 < 4; nb2++) {
                uint32_t b4h[4], b4l[4];
                uint32_t ba = (uint32_t)((ks * 16 + lrow) * 272
                             + (wf0 + nb2 * 16) * 2 + lhalf * 16);
                ldsm4t(b4h, bH + ba);
                ldsm4t(b4l, bL + ba);
#pragma unroll
                for (int half = 0; half < 2; half++) {
                    int n = nb2 * 2 + half;
                    mma16816(acc[0][n], ah[0],  &b4h[half * 2]);
                    mma16816(acc[1][n], ah[1],  &b4h[half * 2]);
                    mma16816(acc[0][n], al2[0], &b4h[half * 2]);
                    mma16816(acc[1][n], al2[1], &b4h[half * 2]);
                    mma16816(acc[0][n], ah[0],  &b4l[half * 2]);
                    mma16816(acc[1][n], ah[1],  &b4l[half * 2]);
                }
            }
        }
        __syncthreads();
    }

    const int r0 = l >> 2, c0 = (l & 3) * 2;
#pragma unroll
    for (int m = 0; m < 2; m++) {
        int row = bm + wi0 + m * 16 + r0;
#pragma unroll
        for (int n = 0; n < 8; n++) {
            int col = bn + wf0 + n * 8 + c0;
            bf162 lo0, lo1;
            bf162 hi0 = split_hi2(acc[m][n][0], acc[m][n][1], lo0);
            bf162 hi1 = split_hi2(acc[m][n][2], acc[m][n][3], lo1);
            *(bf162*)&Ch[(size_t)row * N + col]       = hi0;
            *(bf162*)&Cl[(size_t)row * N + col]       = lo0;
            *(bf162*)&Ch[(size_t)(row + 8) * N + col] = hi1;
            *(bf162*)&Cl[(size_t)(row + 8) * N + col] = lo1;
        }
    }
}

// ============================================================
// el/er from hi/lo bf16 h. One warp per row.
// ============================================================
__global__ __launch_bounds__(256) void eler_kernel(
    const bf16* __restrict__ hh, const bf16* __restrict__ hl,
    const float* __restrict__ a,
    float* __restrict__ el, float* __restrict__ er, int Fo)
{
    int row = (blockIdx.x * blockDim.x + threadIdx.x) >> 5;
    int lane = threadIdx.x & 31;
    if (row >= Bn * Nn) return;
    const bf16* hr = hh + (size_t)row * Fo;
    const bf16* lr = hl + (size_t)row * Fo;
    float sl = 0.f, sr = 0.f;
    for (int f = lane * 2; f < Fo; f += 64) {
        bf162 h2 = *(const bf162*)&hr[f];
        bf162 l2 = *(const bf162*)&lr[f];
        float2 av = *(const float2*)&a[f];
        float2 bv = *(const float2*)&a[Fo + f];
        float v0 = __bfloat162float(h2.x) + __bfloat162float(l2.x);
        float v1 = __bfloat162float(h2.y) + __bfloat162float(l2.y);
        sl += v0 * av.x + v1 * av.y;
        sr += v0 * bv.x + v1 * bv.y;
    }
#pragma unroll
    for (int o = 16; o; o >>= 1) {
        sl += __shfl_xor_sync(0xffffffffu, sl, o);
        sr += __shfl_xor_sync(0xffffffffu, sr, o);
    }
    if (lane == 0) { el[row] = sl; er[row] = sr; }
}

// ============================================================
// per-batch min/max -> (scale, bias)
// ============================================================
__global__ __launch_bounds__(256) void minmax_kernel(
    const float* __restrict__ el, const float* __restrict__ er,
    float* __restrict__ sb)
{
    int b = blockIdx.x, t = threadIdx.x;
    const float* e1 = el + b * Nn;
    const float* e2 = er + b * Nn;
    float mnl = 1e30f, mxl = -1e30f, mnr = 1e30f, mxr = -1e30f;
    for (int i = t; i < Nn; i += 256) {
        float a = e1[i]; mnl = fminf(mnl, a); mxl = fmaxf(mxl, a);
        float c = e2[i]; mnr = fminf(mnr, c); mxr = fmaxf(mxr, c);
    }
#pragma unroll
    for (int o = 16; o; o >>= 1) {
        mnl = fminf(mnl, __shfl_xor_sync(0xffffffffu, mnl, o));
        mxl = fmaxf(mxl, __shfl_xor_sync(0xffffffffu, mxl, o));
        mnr = fminf(mnr, __shfl_xor_sync(0xffffffffu, mnr, o));
        mxr = fmaxf(mxr, __shfl_xor_sync(0xffffffffu, mxr, o));
    }
    __shared__ float s[8][4];
    int w = t >> 5, lane = t & 31;
    if (lane == 0) { s[w][0] = mnl; s[w][1] = mxl; s[w][2] = mnr; s[w][3] = mxr; }
    __syncthreads();
    if (t == 0) {
#pragma unroll
        for (int i = 1; i < 8; i++) {
            mnl = fminf(mnl, s[i][0]); mxl = fmaxf(mxl, s[i][1]);
            mnr = fminf(mnr, s[i][2]); mxr = fmaxf(mxr, s[i][3]);
        }
        float emin = mnl + mnr; emin = emin >= 0.f ? emin : 0.01f * emin;
        float emax = mxl + mxr; emax = emax >= 0.f ? emax : 0.01f * emax;
        float sc = 30.f / (emax - emin);
        sb[b * 2] = sc;
        sb[b * 2 + 1] = -emin * sc - 20.f;
    }
}

// ============================================================
// Fused attention GEMM, cp.async double-buffered B + register-
// pipelined A (sigmoid). Split-bf16 3-product accumulation.
// ============================================================
template<int FH, bool ELU, bool WFC2, bool SPLITOUT>
__global__ __launch_bounds__(256) void att_mma_kernel(
    const float* __restrict__ el, const float* __restrict__ er,
    const float* __restrict__ sb,
    const bf16* __restrict__ hh, const bf16* __restrict__ hl,
    float* __restrict__ outp, bf16* __restrict__ outh, bf16* __restrict__ outl,
    float* __restrict__ fc2)
{
    extern __shared__ char dsm[];
    const uint32_t base = smem_u32(dsm);

    const int t  = threadIdx.x;
    const int b  = blockIdx.z;
    const int i0 = blockIdx.x * 128;
    const int f0 = blockIdx.y * 128;
    const int w  = t >> 5, l = t & 31;
    const int wi0 = (w & 3) * 32;
    const int wf0 = (w >> 2) * 64;

    const float scale = sb[b * 2], bias = sb[b * 2 + 1];
    const float* erb = er + b * Nn;
    const int ai = t >> 1, aj = (t & 1) * 16;
    const float eli = el[b * Nn + i0 + ai];
    const uint32_t aoff = (uint32_t)(ai * 40 + aj) * 2;

    const int bj = t >> 3, bf = (t & 7) * 16;
    const uint32_t boff = (uint32_t)(bj * 136 + bf) * 2;
    const bf16* hhb = hh + (size_t)b * Nn * FH + f0;
    const bf16* hlb = hl + (size_t)b * Nn * FH + f0;

    float acc[2][8][4];
#pragma unroll
    for (int m = 0; m < 2; m++)
#pragma unroll
        for (int n = 0; n < 8; n++)
#pragma unroll
            for (int q = 0; q < 4; q++) acc[m][n][q] = 0.f;

    auto sigmoid16 = [&](int j0, float* sv) {
#pragma unroll
        for (int u = 0; u < 4; u++) {
            float4 e4 = *(const float4*)&erb[j0 + aj + u * 4];
            float xs[4] = {e4.x, e4.y, e4.z, e4.w};
#pragma unroll
            for (int q = 0; q < 4; q++) {
                float x = eli + xs[q];
                x = x >= 0.f ? x : 0.01f * x;
                x = scale * x + bias;
                sv[u * 4 + q] = 1.f / (1.f + __expf(-x));
            }
        }
        if (WFC2) {
            float* fr = fc2 + ((size_t)(b * Nn + i0 + ai)) * Nn + j0 + aj;
#pragma unroll
            for (int u = 0; u < 4; u++)
                *(float4*)&fr[u * 4] =
                    make_float4(sv[u*4], sv[u*4+1], sv[u*4+2], sv[u*4+3]);
        }
    };
    auto sts_a = [&](int s, const float* sv) {
        uint32_t sbA = base + (uint32_t)s * STG_SZ;
        uint32_t hw[8], lw[8];
#pragma unroll
        for (int p = 0; p < 8; p++) {
            bf162 lo;
            bf162 hi = split_hi2(sv[p * 2], sv[p * 2 + 1], lo);
            hw[p] = *(uint32_t*)&hi;
            lw[p] = *(uint32_t*)&lo;
        }
        uint4 v0 = make_uint4(hw[0], hw[1], hw[2], hw[3]);
        uint4 v1 = make_uint4(hw[4], hw[5], hw[6], hw[7]);
        uint4 u0 = make_uint4(lw[0], lw[1], lw[2], lw[3]);
        uint4 u1 = make_uint4(lw[4], lw[5], lw[6], lw[7]);
        *(uint4*)(dsm + (sbA - base) + aoff)              = v0;
        *(uint4*)(dsm + (sbA - base) + aoff + 16)         = v1;
        *(uint4*)(dsm + (sbA - base) + A_ARR + aoff)      = u0;
        *(uint4*)(dsm + (sbA - base) + A_ARR + aoff + 16) = u1;
    };
    auto load_b = [&](int j0, int s) {
        uint32_t bb = base + (uint32_t)s * STG_SZ + 2 * A_ARR;
        const bf16* ph = hhb + (size_t)(j0 + bj) * FH + bf;
        const bf16* pl = hlb + (size_t)(j0 + bj) * FH + bf;
        cp16(bb + boff, ph);           cp16(bb + boff + 16, ph + 8);
        cp16(bb + B_ARR + boff, pl);   cp16(bb + B_ARR + boff + 16, pl + 8);
    };

    const uint32_t lrow = (uint32_t)(l & 15), lhalf = (uint32_t)(l >> 4);
    constexpr int NCH = Nn / 32;

    // prologue: chunk 0
    {
        float sv0[16];
        sigmoid16(0, sv0);
        sts_a(0, sv0);
        load_b(0, 0);
        cp_commit();
    }

    for (int ch = 0; ch < NCH; ch++) {
        const int s = ch & 1;
        if (ch + 1 < NCH) {
            load_b((ch + 1) * 32, s ^ 1);
            cp_commit();
            cp_wait<1>();
        } else {
            cp_wait<0>();
        }
        __syncthreads();
        float svn[16];
        if (ch + 1 < NCH) sigmoid16((ch + 1) * 32, svn);

        const uint32_t aH = base + (uint32_t)s * STG_SZ;
        const uint32_t aL = aH + A_ARR;
        const uint32_t bH = aH + 2 * A_ARR;
        const uint32_t bL = bH + B_ARR;
#pragma unroll
        for (int ks = 0; ks < 2; ks++) {
            uint32_t ah[2][4], al2[2][4];
            uint32_t abase = (uint32_t)((wi0 + lrow) * 80 + ks * 32 + lhalf * 16);
            ldsm4(ah[0],  aH + abase);
            ldsm4(ah[1],  aH + abase + 16 * 80);
            ldsm4(al2[0], aL + abase);
            ldsm4(al2[1], aL + abase + 16 * 80);
#pragma unroll
            for (int nb2 = 0; nb2 < 4; nb2++) {
                uint32_t b4h[4], b4l[4];
                uint32_t ba = (uint32_t)((ks * 16 + lrow) * 272
                             + (wf0 + nb2 * 16) * 2 + lhalf * 16);
                ldsm4t(b4h, bH + ba);
                ldsm4t(b4l, bL + ba);
#pragma unroll
                for (int half = 0; half < 2; half++) {
                    int n = nb2 * 2 + half;
                    mma16816(acc[0][n], ah[0],  &b4h[half * 2]);
                    mma16816(acc[1][n], ah[1],  &b4h[half * 2]);
                    mma16816(acc[0][n], al2[0], &b4h[half * 2]);
                    mma16816(acc[1][n], al2[1], &b4h[half * 2]);
                    mma16816(acc[0][n], ah[0],  &b4l[half * 2]);
                    mma16816(acc[1][n], ah[1],  &b4l[half * 2]);
                }
            }
        }
        __syncthreads();
        if (ch + 1 < NCH) sts_a(s ^ 1, svn);
    }

    // epilogue
    const int r0 = l >> 2, c0 = (l & 3) * 2;
#pragma unroll
    for (int m = 0; m < 2; m++) {
        int row = i0 + wi0 + m * 16 + r0;
#pragma unroll
        for (int n = 0; n < 8; n++) {
            int col = f0 + wf0 + n * 8 + c0;
            float2 v0 = make_float2(acc[m][n][0], acc[m][n][1]);
            float2 v1 = make_float2(acc[m][n][2], acc[m][n][3]);
            if (ELU) {
                v0.x = v0.x > 0.f ? v0.x : __expf(v0.x) - 1.f;
                v0.y = v0.y > 0.f ? v0.y : __expf(v0.y) - 1.f;
                v1.x = v1.x > 0.f ? v1.x : __expf(v1.x) - 1.f;
                v1.y = v1.y > 0.f ? v1.y : __expf(v1.y) - 1.f;
            }
            if (SPLITOUT) {
                bf162 lo0, lo1;
                bf162 hi0 = split_hi2(v0.x, v0.y, lo0);
                bf162 hi1 = split_hi2(v1.x, v1.y, lo1);
                size_t base0 = (size_t)b * Nn * FH + (size_t)row * FH + col;
                size_t base1 = (size_t)b * Nn * FH + (size_t)(row + 8) * FH + col;
                *(bf162*)&outh[base0] = hi0;
                *(bf162*)&outl[base0] = lo0;
                *(bf162*)&outh[base1] = hi1;
                *(bf162*)&outl[base1] = lo1;
            } else {
                float* ob = outp + (size_t)b * Nn * FH;
                *(float2*)&ob[(size_t)row * FH + col]       = v0;
                *(float2*)&ob[(size_t)(row + 8) * FH + col] = v1;
            }
        }
    }
}

// ============================================================
// v[b,j] = g2[b,j,:] . Wg
// ============================================================
__global__ __launch_bounds__(256) void v_kernel(
    const float* __restrict__ g2, const float* __restrict__ Wg,
    float* __restrict__ v)
{
    int row = (blockIdx.x * blockDim.x + threadIdx.x) >> 5;
    int lane = threadIdx.x & 31;
    if (row >= Bn * Nn) return;
    const float* g = g2 + (size_t)row * H2n;
    float s = 0.f;
#pragma unroll
    for (int f = lane; f < H2n; f += 32) s += g[f] * Wg[f];
#pragma unroll
    for (int o = 16; o; o >>= 1) s += __shfl_xor_sync(0xffffffffu, s, o);
    if (lane == 0) v[row] = s;
}

// ============================================================
// out[b,i] = leaky( fc2[b,i,:] . v[b,:] + bg )
// ============================================================
__global__ __launch_bounds__(256) void z_kernel(
    const float* __restrict__ fc2, const float* __restrict__ v,
    const float* __restrict__ bg, float* __restrict__ out)
{
    int row = blockIdx.x;
    int b = row >> 10;
    int t = threadIdx.x;
    const float* fr = fc2 + (size_t)row * Nn;
    const float* vb = v + b * Nn;
    float4 f4 = *(const float4*)&fr[t * 4];
    float4 v4 = *(const float4*)&vb[t * 4];
    float s = f4.x * v4.x + f4.y * v4.y + f4.z * v4.z + f4.w * v4.w;
#pragma unroll
    for (int o = 16; o; o >>= 1) s += __shfl_xor_sync(0xffffffffu, s, o);
    __shared__ float red[8];
    int w = t >> 5, lane = t & 31;
    if (lane == 0) red[w] = s;
    __syncthreads();
    if (t == 0) {
        float z = red[0] + red[1] + red[2] + red[3]
                + red[4] + red[5] + red[6] + red[7] + bg[0];
        out[row] = z >= 0.f ? z : 0.01f * z;
    }
}

// ============================================================
extern "C" void kernel_launch(void* const* d_in, const int* in_sizes, int n_in,
                              void* d_out, int out_size)
{
    const float* x  = (const float*)d_in[0];
    // d_in[1] = edge_weight (unused by reference)
    const float* W1 = (const float*)d_in[2];
    const float* a1 = (const float*)d_in[3];
    const float* W2 = (const float*)d_in[4];
    const float* a2 = (const float*)d_in[5];
    const float* Wg = (const float*)d_in[6];
    const float* bg = (const float*)d_in[7];

    float* out = (float*)d_out;
    float* fc2 = out + (size_t)Bn * Nn;
    float* g2  = fc2 + (size_t)Bn * Nn * Nn;

    bf16 *xh, *xl, *w1h, *w1l, *w2h, *w2l, *h1h, *h1l, *g1h, *g1l, *h2h, *h2l;
    float *el, *er, *sb, *vv;
    cudaGetSymbolAddress((void**)&xh,  g_xh);
    cudaGetSymbolAddress((void**)&xl,  g_xl);
    cudaGetSymbolAddress((void**)&w1h, g_w1h);
    cudaGetSymbolAddress((void**)&w1l, g_w1l);
    cudaGetSymbolAddress((void**)&w2h, g_w2h);
    cudaGetSymbolAddress((void**)&w2l, g_w2l);
    cudaGetSymbolAddress((void**)&h1h, g_h1h);
    cudaGetSymbolAddress((void**)&h1l, g_h1l);
    cudaGetSymbolAddress((void**)&g1h, g_g1h);
    cudaGetSymbolAddress((void**)&g1l, g_g1l);
    cudaGetSymbolAddress((void**)&h2h, g_h2h);
    cudaGetSymbolAddress((void**)&h2l, g_h2l);
    cudaGetSymbolAddress((void**)&el,  g_el);
    cudaGetSymbolAddress((void**)&er,  g_er);
    cudaGetSymbolAddress((void**)&sb,  g_sb);
    cudaGetSymbolAddress((void**)&vv,  g_v);

    const int M = Bn * Nn;   // 32768

    static int smem_set = 0;
    if (!smem_set) {
        cudaFuncSetAttribute(mma_gemm_kernel<FIN>,
            cudaFuncAttributeMaxDynamicSharedMemorySize, DSM_SZ);
        cudaFuncSetAttribute(mma_gemm_kernel<H1n>,
            cudaFuncAttributeMaxDynamicSharedMemorySize, DSM_SZ);
        cudaFuncSetAttribute(att_mma_kernel<H1n, true, false, true>,
            cudaFuncAttributeMaxDynamicSharedMemorySize, DSM_SZ);
        cudaFuncSetAttribute(att_mma_kernel<H2n, false, true, false>,
            cudaFuncAttributeMaxDynamicSharedMemorySize, DSM_SZ);
        smem_set = 1;
    }

    // 0) splits of inputs
    split_kernel<<<(M * FIN / 4 + 255) / 256, 256>>>(x, xh, xl, M * FIN / 4);
    split_kernel<<<(FIN * H1n / 4 + 255) / 256, 256>>>(W1, w1h, w1l, FIN * H1n / 4);
    split_kernel<<<(H1n * H2n / 4 + 255) / 256, 256>>>(W2, w2h, w2l, H1n * H2n / 4);
    // 1) h1 = x @ W1
    mma_gemm_kernel<FIN><<<dim3(H1n / 128, M / 128), 256, DSM_SZ>>>(
        xh, xl, w1h, w1l, h1h, h1l, H1n);
    // 2) el1/er1 + scale/bias
    eler_kernel<<<M / 8, 256>>>(h1h, h1l, a1, el, er, H1n);
    minmax_kernel<<<Bn, 256>>>(el, er, sb);
    // 3) g1 = elu(att1 @ h1)
    att_mma_kernel<H1n, true, false, true>
        <<<dim3(Nn / 128, H1n / 128, Bn), 256, DSM_SZ>>>(el, er, sb, h1h, h1l,
                                                 nullptr, g1h, g1l, nullptr);
    // 4) h2 = g1 @ W2
    mma_gemm_kernel<H1n><<<dim3(H2n / 128, M / 128), 256, DSM_SZ>>>(
        g1h, g1l, w2h, w2l, h2h, h2l, H2n);
    // 5) el2/er2 + scale/bias
    eler_kernel<<<M / 8, 256>>>(h2h, h2l, a2, el, er, H2n);
    minmax_kernel<<<Bn, 256>>>(el, er, sb);
    // 6) fc2 + g2 = att2 @ h2
    att_mma_kernel<H2n, false, true, false>
        <<<dim3(Nn / 128, 1, Bn), 256, DSM_SZ>>>(el, er, sb, h2h, h2l,
                                         g2, nullptr, nullptr, fc2);
    // 7) v = g2 @ Wg
    v_kernel<<<M / 8, 256>>>(g2, Wg, vv);
    // 8) out = leaky(fc2 @ v + bg)
    z_kernel<<<M, 256>>>(fc2, vv, bg, out);
}